// round 2
// baseline (speedup 1.0000x reference)
#include <cuda_runtime.h>
#include <cstdint>

typedef unsigned long long u64;
typedef unsigned int u32;

#define N_ENT     50000
#define N_EDGES   800000
#define D_PE      16
#define NB        768      // blocks: 768 <= 128 SMs * 6 -> always co-resident
#define NT        256
#define NTHR      (NB*NT)  // 196608
#define NW64      782      // ceil(50000/64)
#define NW32      1564     // 2*NW64 (>= ceil(50000/32)=1563)

// ---- device state (no allocations allowed) --------------------------------
__device__ u64 g_front[N_ENT];
__device__ u64 g_next[N_ENT];
__device__ u64 g_vis[N_ENT];
__device__ u64 g_cnt[N_ENT];      // packed byte counts c0|c1<<8|c2<<16|c3<<24
__device__ u32 g_Fbm[NW32];       // frontier-nonempty bitmap (bit n&31 of word n>>5)
__device__ int g_nvalid;
__device__ u32 g_bar_count = 0;   // wraps via atomicInc -> self-resetting
__device__ u32 g_bar_sense = 0;   // monotonically increasing across replays

// grid barrier: sense-reversing, replay-safe via entry-time base offset
__device__ __forceinline__ void gbar(u32 base, u32 k) {
    __syncthreads();
    if (threadIdx.x == 0) {
        __threadfence();
        if (atomicInc(&g_bar_count, NB - 1) == NB - 1) {
            *(volatile u32*)&g_bar_sense = base + k;
        } else {
            while ((u32)(*(volatile u32*)&g_bar_sense - base) < k) {}
        }
    }
    __syncthreads();
}

__device__ __forceinline__ u64 ldcg64(const u64* p) { return __ldcg(p); }

__global__ void __launch_bounds__(NT, 6)
bfs_all(const int* __restrict__ h, const int* __restrict__ t,
        const int* __restrict__ aidx, const float* __restrict__ embed,
        float* __restrict__ out)
{
    __shared__ u32   sF[NW32];        // 6256 B frontier bitmap
    __shared__ float sE[6 * D_PE];    // embedding table
    __shared__ int   svals[64];
    __shared__ int   scnt;

    const int tid  = threadIdx.x;
    const int gtid = blockIdx.x * NT + tid;
    const u32 base = *(volatile u32*)&g_bar_sense;   // stable: no one writes before bar 1

    // ---------------- phase A: zero state ----------------------------------
    for (int n = gtid; n < N_ENT; n += NTHR) {
        g_next[n] = 0ull;
        g_vis[n]  = 0ull;
        g_cnt[n]  = 0ull;
    }
    for (int i = gtid; i < NW32; i += NTHR) g_Fbm[i] = 0u;
    if (tid < 6 * D_PE) sE[tid] = __ldg(embed + tid);
    gbar(base, 1);

    // ---------------- phase B: seed anchors (block 0) ----------------------
    if (blockIdx.x == 0) {
        if (tid == 0) scnt = 0;
        __syncthreads();
        if (tid < 64) {
            int e = __ldg(aidx + (tid & 31));
            svals[tid] = (tid < 32) ? __ldg(h + e) : __ldg(t + e);
        }
        __syncthreads();
        if (tid < 64) {
            int v = svals[tid];
            bool uniq = true;
            for (int j = 0; j < tid; j++) if (svals[j] == v) uniq = false;
            if (uniq) {                 // distinct values -> plain stores are safe
                u64 bit = 1ull << tid;
                g_front[v] = bit;
                g_vis[v]   = bit;
                g_cnt[v]   = 1ull;      // depth-0 count
                atomicOr(&g_Fbm[v >> 5], 1u << (v & 31));
                atomicAdd(&scnt, 1);
            }
        }
        __syncthreads();
        if (tid == 0) g_nvalid = scnt;
    }
    gbar(base, 2);

    // ---------------- BFS rounds (depth 1..4; depth 5 provably a no-op) ----
    u32 k = 2;
    #pragma unroll 1
    for (int depth = 1; depth <= 4; ++depth) {
        // copy frontier bitmap to smem
        for (int i = tid; i < NW32; i += NT) sF[i] = __ldcg(&g_Fbm[i]);
        __syncthreads();

        // edge-parallel push, 4 edges/thread via int4 loads
        #pragma unroll 1
        for (int j = gtid; j < N_EDGES / 4; j += NTHR) {
            int4 S = __ldg((const int4*)h + j);
            int4 D = __ldg((const int4*)t + j);
            #pragma unroll
            for (int q = 0; q < 4; q++) {
                int s = (q == 0) ? S.x : (q == 1) ? S.y : (q == 2) ? S.z : S.w;
                int d = (q == 0) ? D.x : (q == 1) ? D.y : (q == 2) ? D.z : D.w;
                bool fS = (sF[s >> 5] >> (s & 31)) & 1u;
                bool fD = (sF[d >> 5] >> (d & 31)) & 1u;
                if (fS) atomicOr(&g_next[d], ldcg64(&g_front[s]));  // RED.OR
                if (fD) atomicOr(&g_next[s], ldcg64(&g_front[d]));
            }
        }
        gbar(base, ++k);

        if (depth < 4) {
            // update: one warp per 64-entity bitmap word, ballot-built bitmap
            const int gw    = gtid >> 5;
            const int lane  = tid & 31;
            const int shift = 8 * depth;
            #pragma unroll 1
            for (int wi = gw; wi < NW64; wi += (NTHR >> 5)) {
                int n0 = wi * 64 + lane, n1 = n0 + 32;
                u64 nw0 = 0, nw1 = 0;
                if (n0 < N_ENT) {
                    u64 nf = __ldcg(&g_next[n0]);
                    if (nf) {
                        g_next[n0] = 0ull;
                        u64 v = __ldcg(&g_vis[n0]);
                        nw0 = nf & ~v;
                        if (nw0) {
                            g_vis[n0]   = v | nw0;
                            g_cnt[n0]   = __ldcg(&g_cnt[n0]) + ((u64)__popcll(nw0) << shift);
                            g_front[n0] = nw0;
                        }
                    }
                }
                if (n1 < N_ENT) {
                    u64 nf = __ldcg(&g_next[n1]);
                    if (nf) {
                        g_next[n1] = 0ull;
                        u64 v = __ldcg(&g_vis[n1]);
                        nw1 = nf & ~v;
                        if (nw1) {
                            g_vis[n1]   = v | nw1;
                            g_cnt[n1]   = __ldcg(&g_cnt[n1]) + ((u64)__popcll(nw1) << shift);
                            g_front[n1] = nw1;
                        }
                    }
                }
                u32 blo = __ballot_sync(0xffffffffu, nw0 != 0);
                u32 bhi = __ballot_sync(0xffffffffu, nw1 != 0);
                if (lane == 0) { g_Fbm[2*wi] = blo; g_Fbm[2*wi + 1] = bhi; }
            }
            gbar(base, ++k);
        }
    }

    // ---------------- final: depth-4 count + embedding combine -------------
    const int nv = *(volatile int*)&g_nvalid;
    const float inv = 1.0f / (float)nv;
    #pragma unroll 1
    for (int n = gtid; n < N_ENT; n += NTHR) {
        u64 nf = __ldcg(&g_next[n]);
        u64 v  = __ldcg(&g_vis[n]);
        u64 c  = __ldcg(&g_cnt[n]);
        int c4 = __popcll(nf & ~v);
        int c0 = (int)( c        & 0xFF);
        int c1 = (int)((c >> 8)  & 0xFF);
        int c2 = (int)((c >> 16) & 0xFF);
        int c3 = (int)((c >> 24) & 0xFF);
        int rem = nv - (c0 + c1 + c2 + c3 + c4);
        float w0 = c0 * inv, w1 = c1 * inv, w2 = c2 * inv;
        float w3 = c3 * inv, w4 = c4 * inv, w5 = rem * inv;

        float4* o = (float4*)(out + (size_t)n * D_PE);
        #pragma unroll
        for (int q = 0; q < 4; q++) {
            float4 r;
            int b = q * 4;
            r.x = w0*sE[b+0] + w1*sE[D_PE+b+0] + w2*sE[2*D_PE+b+0]
                + w3*sE[3*D_PE+b+0] + w4*sE[4*D_PE+b+0] + w5*sE[5*D_PE+b+0];
            r.y = w0*sE[b+1] + w1*sE[D_PE+b+1] + w2*sE[2*D_PE+b+1]
                + w3*sE[3*D_PE+b+1] + w4*sE[4*D_PE+b+1] + w5*sE[5*D_PE+b+1];
            r.z = w0*sE[b+2] + w1*sE[D_PE+b+2] + w2*sE[2*D_PE+b+2]
                + w3*sE[3*D_PE+b+2] + w4*sE[4*D_PE+b+2] + w5*sE[5*D_PE+b+2];
            r.w = w0*sE[b+3] + w1*sE[D_PE+b+3] + w2*sE[2*D_PE+b+3]
                + w3*sE[3*D_PE+b+3] + w4*sE[4*D_PE+b+3] + w5*sE[5*D_PE+b+3];
            o[q] = r;
        }
    }
}

// ---------------------------------------------------------------------------
extern "C" void kernel_launch(void* const* d_in, const int* in_sizes, int n_in,
                              void* d_out, int out_size) {
    const int*   h     = (const int*)d_in[0];   // [800000]
    const int*   t     = (const int*)d_in[1];   // [800000]
    const int*   aidx  = (const int*)d_in[2];   // [32]
    const float* embed = (const float*)d_in[4]; // [6,16]
    float*       out   = (float*)d_out;         // [50000,16]

    bfs_all<<<NB, NT>>>(h, t, aidx, embed, out);
}